// round 7
// baseline (speedup 1.0000x reference)
#include <cuda_runtime.h>
#include <cuda_fp16.h>
#include <math.h>
#include <stdint.h>

// ---------------------------------------------------------------------------
// Problem constants
// ---------------------------------------------------------------------------
#define BATCH   2
#define SEQ     2048
#define DMODEL  1024
#define DFF     4096
#define NHEADS  16
#define DHEAD   64
#define ROWS    (BATCH * SEQ)
#define LN_EPS  1e-5f

// ---------------------------------------------------------------------------
// Scratch — __device__ globals
// ---------------------------------------------------------------------------
__device__ __half g_xh  [(size_t)ROWS * DMODEL];
__device__ __half g_qkv [(size_t)ROWS * 3 * DMODEL];
__device__ __half g_attn[(size_t)ROWS * DMODEL];
__device__ __half g_ffn [(size_t)ROWS * DFF];
__device__ float  g_h1  [(size_t)ROWS * DMODEL];
__device__ __half g_h1h [(size_t)ROWS * DMODEL];
__device__ float  g_tmp [(size_t)ROWS * DMODEL];
__device__ __half g_wt  [(size_t)12288 * 1024];

#define WT_QKV 0
#define WT_O   (3072 * 1024)
#define WT_1   (WT_O + 1024 * 1024)
#define WT_2   (WT_1 + 4096 * 1024)

// ---------------------------------------------------------------------------
// helpers
// ---------------------------------------------------------------------------
__device__ __forceinline__ unsigned pack2(float x, float y) {
    __half2 h = __floats2half2_rn(x, y);
    return *reinterpret_cast<unsigned*>(&h);
}

__device__ __forceinline__ void mma_f16(float c[4], const unsigned a[4],
                                        const unsigned b[2]) {
    asm volatile(
        "mma.sync.aligned.m16n8k16.row.col.f32.f16.f16.f32 "
        "{%0,%1,%2,%3},{%4,%5,%6,%7},{%8,%9},{%0,%1,%2,%3};"
        : "+f"(c[0]), "+f"(c[1]), "+f"(c[2]), "+f"(c[3])
        : "r"(a[0]), "r"(a[1]), "r"(a[2]), "r"(a[3]), "r"(b[0]), "r"(b[1]));
}

__device__ __forceinline__ unsigned smaddr(const void* p) {
    unsigned a;
    asm("{\n\t.reg .u64 t;\n\tcvta.to.shared.u64 t, %1;\n\tcvt.u32.u64 %0, t;\n\t}"
        : "=r"(a) : "l"(p));
    return a;
}

__device__ __forceinline__ void ldmx4(unsigned r[4], unsigned a) {
    asm volatile("ldmatrix.sync.aligned.m8n8.x4.shared.b16 {%0,%1,%2,%3}, [%4];"
        : "=r"(r[0]), "=r"(r[1]), "=r"(r[2]), "=r"(r[3]) : "r"(a));
}
__device__ __forceinline__ void ldmx4t(unsigned r[4], unsigned a) {
    asm volatile("ldmatrix.sync.aligned.m8n8.x4.trans.shared.b16 {%0,%1,%2,%3}, [%4];"
        : "=r"(r[0]), "=r"(r[1]), "=r"(r[2]), "=r"(r[3]) : "r"(a));
}

__device__ __forceinline__ void cp16(unsigned dst, const void* src) {
    asm volatile("cp.async.cg.shared.global [%0], [%1], 16;"
                 :: "r"(dst), "l"(src));
}
#define CP_COMMIT() asm volatile("cp.async.commit_group;" ::: "memory")
#define CP_WAIT1()  asm volatile("cp.async.wait_group 1;"  ::: "memory")

__device__ __forceinline__ float gelu_exact(float x) {
    return 0.5f * x * (1.f + erff(x * 0.70710678118654752f));
}

// ---------------------------------------------------------------------------
// X -> fp16
// ---------------------------------------------------------------------------
__global__ __launch_bounds__(256)
void f2h_kernel(const float* __restrict__ in, __half* __restrict__ out)
{
    int i = blockIdx.x * 256 + threadIdx.x;
    float4 v = ((const float4*)in)[i];
    uint2 u;
    u.x = pack2(v.x, v.y);
    u.y = pack2(v.z, v.w);
    ((uint2*)out)[i] = u;
}

// ---------------------------------------------------------------------------
// Weight transpose + fp16 convert
// ---------------------------------------------------------------------------
__global__ __launch_bounds__(256)
void transpose_h(const float* __restrict__ in, __half* __restrict__ out,
                 int R, int C)
{
    __shared__ float tile[32][33];
    const int c0 = blockIdx.x * 32, r0 = blockIdx.y * 32;
    const int tx = threadIdx.x & 31, ty = threadIdx.x >> 5;
#pragma unroll
    for (int i = ty; i < 32; i += 8)
        tile[i][tx] = in[(size_t)(r0 + i) * C + c0 + tx];
    __syncthreads();
#pragma unroll
    for (int i = ty; i < 32; i += 8)
        out[(size_t)(c0 + i) * R + r0 + tx] = __float2half(tile[tx][i]);
}

// ---------------------------------------------------------------------------
// fp16 GEMM v3: BM=128, BN=256, BK=32, 256 threads (8 warps 2x4),
// warp tile 64x64, 3-stage cp.async, ldmatrix fragments.
// C[M,N] = act(A[M,K] @ Bt[N,K]^T + bias[N])
// ---------------------------------------------------------------------------
#define PITCH 40
#define AT_H (128 * PITCH)             // A tile halfs
#define BT_H (256 * PITCH)             // B tile halfs
#define STAGE_H (AT_H + BT_H)
#define GT_SMEM (3 * STAGE_H * 2)      // 92160 B

template<bool OH, int ACT>
__global__ __launch_bounds__(256, 1)
void hgemm3(const __half* __restrict__ A, const __half* __restrict__ Bt,
            const float* __restrict__ bias, void* __restrict__ Cv,
            int M, int N, int K)
{
    extern __shared__ __half sm2[];
    const unsigned sbase = smaddr(sm2);

    const int tid = threadIdx.x, lane = tid & 31, warp = tid >> 5;
    const int wm = warp >> 2, wn = warp & 3;
    const int g = lane >> 2, tg = lane & 3;
    const int bx = blockIdx.x, by = blockIdx.y;

    const __half* Abase = A  + (size_t)(by * 128) * K;
    const __half* Bbase = Bt + (size_t)(bx * 256) * K;
    const int KT = K / 32;

    // A: 512 16B-chunks, B: 1024 16B-chunks; 2 + 4 per thread
    const int ar0 = tid >> 2,          akc0 = (tid & 3) * 8;
    const int ar1 = (tid + 256) >> 2,  akc1 = ((tid + 256) & 3) * 8;

    auto issue = [&](int kt, int slot) {
        const unsigned sa = sbase + (unsigned)(slot * STAGE_H) * 2;
        const unsigned sb = sa + (unsigned)AT_H * 2;
        const int ko = kt * 32;
        cp16(sa + (ar0 * PITCH + akc0) * 2, Abase + (size_t)ar0 * K + ko + akc0);
        cp16(sa + (ar1 * PITCH + akc1) * 2, Abase + (size_t)ar1 * K + ko + akc1);
#pragma unroll
        for (int i = 0; i < 4; i++) {
            int f = tid + 256 * i;
            int r = f >> 2, kc = (f & 3) * 8;
            cp16(sb + (r * PITCH + kc) * 2, Bbase + (size_t)r * K + ko + kc);
        }
    };

    float c[4][8][4];
#pragma unroll
    for (int mi = 0; mi < 4; mi++)
#pragma unroll
        for (int ni = 0; ni < 8; ni++)
#pragma unroll
            for (int k = 0; k < 4; k++) c[mi][ni][k] = 0.f;

    issue(0, 0); CP_COMMIT();
    if (KT > 1) issue(1, 1);
    CP_COMMIT();

    const int a_row = (lane & 15);
    const int a_col = (lane >> 4) * 8;
    const int b_row = ((lane >> 4) << 3) + (lane & 7);
    const int b_col = ((lane >> 3) & 1) * 8;

    for (int kt = 0; kt < KT; kt++) {
        CP_WAIT1();
        __syncthreads();
        const int kn = kt + 2;
        if (kn < KT) issue(kn, kn % 3);
        CP_COMMIT();

        const unsigned abase = sbase + (unsigned)((kt % 3) * STAGE_H) * 2;
        const unsigned bbase = abase + (unsigned)AT_H * 2;

#pragma unroll
        for (int ks = 0; ks < 2; ks++) {
            unsigned af[4][4], bf[8][2];
#pragma unroll
            for (int mi = 0; mi < 4; mi++)
                ldmx4(af[mi], abase +
                      ((wm * 64 + mi * 16 + a_row) * PITCH + ks * 16 + a_col) * 2);
#pragma unroll
            for (int p = 0; p < 4; p++) {
                unsigned r[4];
                ldmx4(r, bbase +
                      ((wn * 64 + 16 * p + b_row) * PITCH + ks * 16 + b_col) * 2);
                bf[2 * p][0] = r[0]; bf[2 * p][1] = r[1];
                bf[2 * p + 1][0] = r[2]; bf[2 * p + 1][1] = r[3];
            }
#pragma unroll
            for (int mi = 0; mi < 4; mi++)
#pragma unroll
                for (int ni = 0; ni < 8; ni++)
                    mma_f16(c[mi][ni], af[mi], bf[ni]);
        }
    }

    // epilogue
#pragma unroll
    for (int mi = 0; mi < 4; mi++) {
        int row = by * 128 + wm * 64 + mi * 16 + g;
#pragma unroll
        for (int ni = 0; ni < 8; ni++) {
            int col = bx * 256 + wn * 64 + ni * 8 + tg * 2;
            float b0 = bias[col], b1 = bias[col + 1];
            float v00 = c[mi][ni][0] + b0, v01 = c[mi][ni][1] + b1;
            float v10 = c[mi][ni][2] + b0, v11 = c[mi][ni][3] + b1;
            if (ACT == 1) {
                v00 = gelu_exact(v00); v01 = gelu_exact(v01);
                v10 = gelu_exact(v10); v11 = gelu_exact(v11);
            }
            if (OH) {
                __half* C = (__half*)Cv;
                *(__half2*)&C[(size_t)row * N + col] = __floats2half2_rn(v00, v01);
                *(__half2*)&C[(size_t)(row + 8) * N + col] = __floats2half2_rn(v10, v11);
            } else {
                float* C = (float*)Cv;
                *(float2*)&C[(size_t)row * N + col]       = make_float2(v00, v01);
                *(float2*)&C[(size_t)(row + 8) * N + col] = make_float2(v10, v11);
            }
        }
    }
}

// ---------------------------------------------------------------------------
// Flash attention v3 (unchanged from R6 win)
// ---------------------------------------------------------------------------
#define QH 4608
#define ATT_SMEM (7 * QH * 2)

__global__ __launch_bounds__(128)
void attn_h3_kernel(const __half* __restrict__ qkv, __half* __restrict__ out)
{
    extern __shared__ __half ash[];
    const unsigned sbase = smaddr(ash);

    const int qt = gridDim.x - 1 - blockIdx.x;
    const int h = blockIdx.y, b = blockIdx.z;
    const int t = threadIdx.x, lane = t & 31, w = t >> 5;
    const int g = lane >> 2, tg = lane & 3;

    const int lr[4] = { t >> 3, (t + 128) >> 3, (t + 256) >> 3, (t + 384) >> 3 };
    const int lc    = (t & 7) * 8;

    const __half* qbase = qkv + (size_t)(b * SEQ + qt * 64) * (3 * DMODEL) + h * DHEAD;
#pragma unroll
    for (int i = 0; i < 4; i++)
        *(uint4*)&ash[lr[i] * 72 + lc] =
            *(const uint4*)(qbase + (size_t)lr[i] * (3 * DMODEL) + lc);

    auto issue = [&](int kt, int buf) {
        const __half* kb = qkv + (size_t)(b * SEQ + kt * 64) * (3 * DMODEL)
                         + DMODEL + h * DHEAD;
        const __half* vb = kb + DMODEL;
        const unsigned kd = sbase + (unsigned)(QH * (1 + buf)) * 2;
        const unsigned vd = sbase + (unsigned)(QH * (4 + buf)) * 2;
#pragma unroll
        for (int i = 0; i < 4; i++) {
            cp16(kd + (lr[i] * 72 + lc) * 2, kb + (size_t)lr[i] * (3 * DMODEL) + lc);
            cp16(vd + (lr[i] * 72 + lc) * 2, vb + (size_t)lr[i] * (3 * DMODEL) + lc);
        }
    };

    issue(0, 0); CP_COMMIT();
    if (qt >= 1) issue(1, 1);
    CP_COMMIT();
    __syncthreads();

    const int a_row = (lane & 15), a_col = (lane >> 4) * 8;
    unsigned qf[4][4];
#pragma unroll
    for (int ks = 0; ks < 4; ks++)
        ldmx4(qf[ks], sbase + ((w * 16 + a_row) * 72 + ks * 16 + a_col) * 2);

    const int b_row = ((lane >> 4) << 3) + (lane & 7);
    const int b_col = ((lane >> 3) & 1) * 8;
    const int v_row = ((lane >> 3) & 1) * 8 + (lane & 7);
    const int v_col = (lane >> 4) * 8;

    float m0 = -INFINITY, m1 = -INFINITY, l0 = 0.f, l1 = 0.f;
    float co[8][4];
#pragma unroll
    for (int ni = 0; ni < 8; ni++)
#pragma unroll
        for (int k = 0; k < 4; k++) co[ni][k] = 0.f;

    const int qr = qt * 64 + w * 16 + g;

    for (int kt = 0; kt <= qt; kt++) {
        CP_WAIT1();
        __syncthreads();
        const int buf = kt % 3;
        const unsigned kb = sbase + (unsigned)(QH * (1 + buf)) * 2;
        const unsigned vb = sbase + (unsigned)(QH * (4 + buf)) * 2;

        float cs[8][4];
#pragma unroll
        for (int ni = 0; ni < 8; ni++)
#pragma unroll
            for (int k = 0; k < 4; k++) cs[ni][k] = 0.f;

#pragma unroll
        for (int ks = 0; ks < 4; ks++) {
            unsigned bf[8][2];
#pragma unroll
            for (int p = 0; p < 4; p++) {
                unsigned r[4];
                ldmx4(r, kb + ((16 * p + b_row) * 72 + ks * 16 + b_col) * 2);
                bf[2 * p][0] = r[0]; bf[2 * p][1] = r[1];
                bf[2 * p + 1][0] = r[2]; bf[2 * p + 1][1] = r[3];
            }
#pragma unroll
            for (int ni = 0; ni < 8; ni++)
                mma_f16(cs[ni], qf[ks], bf[ni]);
        }

        const bool diag = (kt == qt);
#pragma unroll
        for (int ni = 0; ni < 8; ni++) {
            cs[ni][0] *= 0.125f; cs[ni][1] *= 0.125f;
            cs[ni][2] *= 0.125f; cs[ni][3] *= 0.125f;
            if (diag) {
                int kg = kt * 64 + ni * 8 + tg * 2;
                if (kg     > qr)     cs[ni][0] = -INFINITY;
                if (kg + 1 > qr)     cs[ni][1] = -INFINITY;
                if (kg     > qr + 8) cs[ni][2] = -INFINITY;
                if (kg + 1 > qr + 8) cs[ni][3] = -INFINITY;
            }
        }

        float mx0 = -INFINITY, mx1 = -INFINITY;
#pragma unroll
        for (int ni = 0; ni < 8; ni++) {
            mx0 = fmaxf(mx0, fmaxf(cs[ni][0], cs[ni][1]));
            mx1 = fmaxf(mx1, fmaxf(cs[ni][2], cs[ni][3]));
        }
        mx0 = fmaxf(mx0, __shfl_xor_sync(0xffffffffu, mx0, 1));
        mx0 = fmaxf(mx0, __shfl_xor_sync(0xffffffffu, mx0, 2));
        mx1 = fmaxf(mx1, __shfl_xor_sync(0xffffffffu, mx1, 1));
        mx1 = fmaxf(mx1, __shfl_xor_sync(0xffffffffu, mx1, 2));

        float mt0 = fmaxf(m0, mx0), mt1 = fmaxf(m1, mx1);
        float a0 = __expf(m0 - mt0), a1 = __expf(m1 - mt1);
        m0 = mt0; m1 = mt1;

        float ps0 = 0.f, ps1 = 0.f;
#pragma unroll
        for (int ni = 0; ni < 8; ni++) {
            cs[ni][0] = __expf(cs[ni][0] - mt0);
            cs[ni][1] = __expf(cs[ni][1] - mt0);
            cs[ni][2] = __expf(cs[ni][2] - mt1);
            cs[ni][3] = __expf(cs[ni][3] - mt1);
            ps0 += cs[ni][0] + cs[ni][1];
            ps1 += cs[ni][2] + cs[ni][3];
        }
        ps0 += __shfl_xor_sync(0xffffffffu, ps0, 1);
        ps0 += __shfl_xor_sync(0xffffffffu, ps0, 2);
        ps1 += __shfl_xor_sync(0xffffffffu, ps1, 1);
        ps1 += __shfl_xor_sync(0xffffffffu, ps1, 2);
        l0 = l0 * a0 + ps0;
        l1 = l1 * a1 + ps1;

#pragma unroll
        for (int ni = 0; ni < 8; ni++) {
            co[ni][0] *= a0; co[ni][1] *= a0;
            co[ni][2] *= a1; co[ni][3] *= a1;
        }

#pragma unroll
        for (int ks = 0; ks < 4; ks++) {
            unsigned af[4];
            af[0] = pack2(cs[2 * ks][0],     cs[2 * ks][1]);
            af[1] = pack2(cs[2 * ks][2],     cs[2 * ks][3]);
            af[2] = pack2(cs[2 * ks + 1][0], cs[2 * ks + 1][1]);
            af[3] = pack2(cs[2 * ks + 1][2], cs[2 * ks + 1][3]);
            unsigned bf[8][2];
#pragma unroll
            for (int p = 0; p < 4; p++) {
                unsigned r[4];
                ldmx4t(r, vb + ((ks * 16 + v_row) * 72 + 16 * p + v_col) * 2);
                bf[2 * p][0] = r[0]; bf[2 * p][1] = r[1];
                bf[2 * p + 1][0] = r[2]; bf[2 * p + 1][1] = r[3];
            }
#pragma unroll
            for (int ni = 0; ni < 8; ni++)
                mma_f16(co[ni], af, bf[ni]);
        }

        if (kt + 2 <= qt) issue(kt + 2, (kt + 2) % 3);
        CP_COMMIT();
    }

    float llo = 1.f / l0, lhi = 1.f / l1;
    int row0 = b * SEQ + qt * 64 + w * 16 + g;
    __half* ob = out + (size_t)row0 * DMODEL + h * DHEAD;
#pragma unroll
    for (int ni = 0; ni < 8; ni++) {
        int col = ni * 8 + tg * 2;
        *(__half2*)&ob[col] =
            __floats2half2_rn(co[ni][0] * llo, co[ni][1] * llo);
        *(__half2*)&ob[(size_t)8 * DMODEL + col] =
            __floats2half2_rn(co[ni][2] * lhi, co[ni][3] * lhi);
    }
}

// ---------------------------------------------------------------------------
// Fused residual add + LayerNorm (+ optional fp16 copy)
// ---------------------------------------------------------------------------
template<bool H16>
__global__ __launch_bounds__(256)
void ln_kernel(const float* __restrict__ A, const float* __restrict__ B,
               const float* __restrict__ g, const float* __restrict__ be,
               float* __restrict__ out, __half* __restrict__ out16)
{
    const int row = blockIdx.x;
    const size_t off = (size_t)row * DMODEL;
    const int t = threadIdx.x;

    float4 a = ((const float4*)(A + off))[t];
    float4 b = ((const float4*)(B + off))[t];
    float x0 = a.x + b.x, x1 = a.y + b.y, x2 = a.z + b.z, x3 = a.w + b.w;

    float s  = x0 + x1 + x2 + x3;
    float s2 = x0 * x0 + x1 * x1 + x2 * x2 + x3 * x3;
#pragma unroll
    for (int o = 16; o; o >>= 1) {
        s  += __shfl_xor_sync(0xffffffffu, s, o);
        s2 += __shfl_xor_sync(0xffffffffu, s2, o);
    }
    __shared__ float ws[8], ws2[8];
    if ((t & 31) == 0) { ws[t >> 5] = s; ws2[t >> 5] = s2; }
    __syncthreads();
    s = 0.f; s2 = 0.f;
#pragma unroll
    for (int i = 0; i < 8; i++) { s += ws[i]; s2 += ws2[i]; }

    const float mean = s * (1.f / DMODEL);
    const float var  = s2 * (1.f / DMODEL) - mean * mean;
    const float rstd = rsqrtf(var + LN_EPS);

    float4 gg = ((const float4*)g)[t];
    float4 bb = ((const float4*)be)[t];
    float4 y;
    y.x = (x0 - mean) * rstd * gg.x + bb.x;
    y.y = (x1 - mean) * rstd * gg.y + bb.y;
    y.z = (x2 - mean) * rstd * gg.z + bb.z;
    y.w = (x3 - mean) * rstd * gg.w + bb.w;
    ((float4*)(out + off))[t] = y;
    if (H16) {
        uint2 u;
        u.x = pack2(y.x, y.y);
        u.y = pack2(y.z, y.w);
        ((uint2*)(out16 + off))[t] = u;
    }
}

// ---------------------------------------------------------------------------
// Launcher
// ---------------------------------------------------------------------------
extern "C" void kernel_launch(void* const* d_in, const int* in_sizes, int n_in,
                              void* d_out, int out_size)
{
    const float* X     = (const float*)d_in[0];
    const float* W_qkv = (const float*)d_in[1];
    const float* b_qkv = (const float*)d_in[2];
    const float* W_o   = (const float*)d_in[3];
    const float* b_o   = (const float*)d_in[4];
    const float* W_1   = (const float*)d_in[5];
    const float* b_1   = (const float*)d_in[6];
    const float* W_2   = (const float*)d_in[7];
    const float* b_2   = (const float*)d_in[8];
    const float* ln1g  = (const float*)d_in[9];
    const float* ln1b  = (const float*)d_in[10];
    const float* ln2g  = (const float*)d_in[11];
    const float* ln2b  = (const float*)d_in[12];
    float* out = (float*)d_out;

    __half *xh, *qkv, *attn, *ffn, *h1h, *wt;
    float *h1, *tmp;
    cudaGetSymbolAddress((void**)&xh,   g_xh);
    cudaGetSymbolAddress((void**)&qkv,  g_qkv);
    cudaGetSymbolAddress((void**)&attn, g_attn);
    cudaGetSymbolAddress((void**)&ffn,  g_ffn);
    cudaGetSymbolAddress((void**)&h1,   g_h1);
    cudaGetSymbolAddress((void**)&h1h,  g_h1h);
    cudaGetSymbolAddress((void**)&tmp,  g_tmp);
    cudaGetSymbolAddress((void**)&wt,   g_wt);

    cudaFuncSetAttribute(hgemm3<true, 0>,
                         cudaFuncAttributeMaxDynamicSharedMemorySize, GT_SMEM);
    cudaFuncSetAttribute(hgemm3<false, 0>,
                         cudaFuncAttributeMaxDynamicSharedMemorySize, GT_SMEM);
    cudaFuncSetAttribute(hgemm3<true, 1>,
                         cudaFuncAttributeMaxDynamicSharedMemorySize, GT_SMEM);
    cudaFuncSetAttribute(attn_h3_kernel,
                         cudaFuncAttributeMaxDynamicSharedMemorySize, ATT_SMEM);

    // 0) conversions
    f2h_kernel<<<ROWS * DMODEL / 1024, 256>>>(X, xh);
    transpose_h<<<dim3(3 * DMODEL / 32, DMODEL / 32), 256>>>(W_qkv, wt + WT_QKV, DMODEL, 3 * DMODEL);
    transpose_h<<<dim3(DMODEL / 32, DMODEL / 32), 256>>>(W_o, wt + WT_O, DMODEL, DMODEL);
    transpose_h<<<dim3(DFF / 32, DMODEL / 32), 256>>>(W_1, wt + WT_1, DMODEL, DFF);
    transpose_h<<<dim3(DMODEL / 32, DFF / 32), 256>>>(W_2, wt + WT_2, DFF, DMODEL);

    // 1) QKV projection
    hgemm3<true, 0><<<dim3(3 * DMODEL / 256, ROWS / 128), 256, GT_SMEM>>>(
        xh, wt + WT_QKV, b_qkv, qkv, ROWS, 3 * DMODEL, DMODEL);

    // 2) causal flash attention
    attn_h3_kernel<<<dim3(SEQ / 64, NHEADS, BATCH), 128, ATT_SMEM>>>(qkv, attn);

    // 3) output projection -> tmp (fp32)
    hgemm3<false, 0><<<dim3(DMODEL / 256, ROWS / 128), 256, GT_SMEM>>>(
        attn, wt + WT_O, b_o, tmp, ROWS, DMODEL, DMODEL);

    // 4) H1 = LN(X + O), fp32 + fp16
    ln_kernel<true><<<ROWS, 256>>>(X, tmp, ln1g, ln1b, h1, h1h);

    // 5) FF1 + GELU
    hgemm3<true, 1><<<dim3(DFF / 256, ROWS / 128), 256, GT_SMEM>>>(
        h1h, wt + WT_1, b_1, ffn, ROWS, DFF, DMODEL);

    // 6) FF2 -> tmp (fp32)
    hgemm3<false, 0><<<dim3(DMODEL / 256, ROWS / 128), 256, GT_SMEM>>>(
        ffn, wt + WT_2, b_2, tmp, ROWS, DMODEL, DFF);

    // 7) out = LN(H1 + H2)
    ln_kernel<false><<<ROWS, 256>>>(h1, tmp, ln2g, ln2b, out, nullptr);
}

// round 8
// speedup vs baseline: 1.0644x; 1.0644x over previous
#include <cuda_runtime.h>
#include <cuda_fp16.h>
#include <math.h>
#include <stdint.h>

// ---------------------------------------------------------------------------
// Problem constants
// ---------------------------------------------------------------------------
#define BATCH   2
#define SEQ     2048
#define DMODEL  1024
#define DFF     4096
#define NHEADS  16
#define DHEAD   64
#define ROWS    (BATCH * SEQ)
#define LN_EPS  1e-5f

// ---------------------------------------------------------------------------
// Scratch — __device__ globals
// ---------------------------------------------------------------------------
__device__ __half g_xh  [(size_t)ROWS * DMODEL];
__device__ __half g_qkv [(size_t)ROWS * 3 * DMODEL];
__device__ __half g_attn[(size_t)ROWS * DMODEL];
__device__ __half g_ffn [(size_t)ROWS * DFF];
__device__ float  g_h1  [(size_t)ROWS * DMODEL];
__device__ __half g_h1h [(size_t)ROWS * DMODEL];
__device__ float  g_tmp [(size_t)ROWS * DMODEL];
__device__ __half g_wt  [(size_t)12288 * 1024];

#define WT_QKV 0
#define WT_O   (3072 * 1024)
#define WT_1   (WT_O + 1024 * 1024)
#define WT_2   (WT_1 + 4096 * 1024)

// ---------------------------------------------------------------------------
// helpers
// ---------------------------------------------------------------------------
__device__ __forceinline__ unsigned pack2(float x, float y) {
    __half2 h = __floats2half2_rn(x, y);
    return *reinterpret_cast<unsigned*>(&h);
}

__device__ __forceinline__ void mma_f16(float c[4], const unsigned a[4],
                                        const unsigned b[2]) {
    asm volatile(
        "mma.sync.aligned.m16n8k16.row.col.f32.f16.f16.f32 "
        "{%0,%1,%2,%3},{%4,%5,%6,%7},{%8,%9},{%0,%1,%2,%3};"
        : "+f"(c[0]), "+f"(c[1]), "+f"(c[2]), "+f"(c[3])
        : "r"(a[0]), "r"(a[1]), "r"(a[2]), "r"(a[3]), "r"(b[0]), "r"(b[1]));
}

__device__ __forceinline__ unsigned smaddr(const void* p) {
    unsigned a;
    asm("{\n\t.reg .u64 t;\n\tcvta.to.shared.u64 t, %1;\n\tcvt.u32.u64 %0, t;\n\t}"
        : "=r"(a) : "l"(p));
    return a;
}

__device__ __forceinline__ void ldmx4(unsigned r[4], unsigned a) {
    asm volatile("ldmatrix.sync.aligned.m8n8.x4.shared.b16 {%0,%1,%2,%3}, [%4];"
        : "=r"(r[0]), "=r"(r[1]), "=r"(r[2]), "=r"(r[3]) : "r"(a));
}
__device__ __forceinline__ void ldmx4t(unsigned r[4], unsigned a) {
    asm volatile("ldmatrix.sync.aligned.m8n8.x4.trans.shared.b16 {%0,%1,%2,%3}, [%4];"
        : "=r"(r[0]), "=r"(r[1]), "=r"(r[2]), "=r"(r[3]) : "r"(a));
}

__device__ __forceinline__ void cp16(unsigned dst, const void* src) {
    asm volatile("cp.async.cg.shared.global [%0], [%1], 16;"
                 :: "r"(dst), "l"(src));
}
#define CP_COMMIT() asm volatile("cp.async.commit_group;" ::: "memory")
#define CP_WAIT1()  asm volatile("cp.async.wait_group 1;"  ::: "memory")

__device__ __forceinline__ float gelu_exact(float x) {
    return 0.5f * x * (1.f + erff(x * 0.70710678118654752f));
}

// ---------------------------------------------------------------------------
// X -> fp16
// ---------------------------------------------------------------------------
__global__ __launch_bounds__(256)
void f2h_kernel(const float* __restrict__ in, __half* __restrict__ out)
{
    int i = blockIdx.x * 256 + threadIdx.x;
    float4 v = ((const float4*)in)[i];
    uint2 u;
    u.x = pack2(v.x, v.y);
    u.y = pack2(v.z, v.w);
    ((uint2*)out)[i] = u;
}

// ---------------------------------------------------------------------------
// Weight transpose + fp16 convert
// ---------------------------------------------------------------------------
__global__ __launch_bounds__(256)
void transpose_h(const float* __restrict__ in, __half* __restrict__ out,
                 int R, int C)
{
    __shared__ float tile[32][33];
    const int c0 = blockIdx.x * 32, r0 = blockIdx.y * 32;
    const int tx = threadIdx.x & 31, ty = threadIdx.x >> 5;
#pragma unroll
    for (int i = ty; i < 32; i += 8)
        tile[i][tx] = in[(size_t)(r0 + i) * C + c0 + tx];
    __syncthreads();
#pragma unroll
    for (int i = ty; i < 32; i += 8)
        out[(size_t)(c0 + i) * R + r0 + tx] = __float2half(tile[tx][i]);
}

// ---------------------------------------------------------------------------
// fp16 GEMM (R6 config — known 496us baseline): BM=BN=128, BK=32,
// 256 threads (8 warps 2x4), warp tile 64x32, 3-stage cp.async + ldmatrix.
// ---------------------------------------------------------------------------
#define PITCH 40
#define TILE_H (128 * PITCH)
#define STAGE_H (2 * TILE_H)
#define GT_SMEM (3 * STAGE_H * 2)

template<bool OH, int ACT>
__global__ __launch_bounds__(256)
void hgemm2(const __half* __restrict__ A, const __half* __restrict__ Bt,
            const float* __restrict__ bias, void* __restrict__ Cv,
            int M, int N, int K)
{
    extern __shared__ __half sm2[];
    const unsigned sbase = smaddr(sm2);

    const int tid = threadIdx.x, lane = tid & 31, warp = tid >> 5;
    const int wm = warp >> 2, wn = warp & 3;
    const int g = lane >> 2, tg = lane & 3;
    const int bx = blockIdx.x, by = blockIdx.y;

    const __half* Abase = A  + (size_t)(by * 128) * K;
    const __half* Bbase = Bt + (size_t)(bx * 128) * K;
    const int KT = K / 32;

    const int r0c = tid >> 2, kc0 = (tid & 3) * 8;
    const int r1c = (tid + 256) >> 2, kc1 = ((tid + 256) & 3) * 8;

    auto issue = [&](int kt, int slot) {
        const unsigned sa = sbase + (unsigned)(slot * STAGE_H) * 2;
        const unsigned sb = sa + (unsigned)TILE_H * 2;
        const int ko = kt * 32;
        cp16(sa + (r0c * PITCH + kc0) * 2, Abase + (size_t)r0c * K + ko + kc0);
        cp16(sa + (r1c * PITCH + kc1) * 2, Abase + (size_t)r1c * K + ko + kc1);
        cp16(sb + (r0c * PITCH + kc0) * 2, Bbase + (size_t)r0c * K + ko + kc0);
        cp16(sb + (r1c * PITCH + kc1) * 2, Bbase + (size_t)r1c * K + ko + kc1);
    };

    float c[4][4][4];
#pragma unroll
    for (int mi = 0; mi < 4; mi++)
#pragma unroll
        for (int ni = 0; ni < 4; ni++)
#pragma unroll
            for (int k = 0; k < 4; k++) c[mi][ni][k] = 0.f;

    issue(0, 0); CP_COMMIT();
    if (KT > 1) issue(1, 1);
    CP_COMMIT();

    const int a_row = (lane & 15);
    const int a_col = (lane >> 4) * 8;
    const int b_row = ((lane >> 4) << 3) + (lane & 7);
    const int b_col = ((lane >> 3) & 1) * 8;

    for (int kt = 0; kt < KT; kt++) {
        CP_WAIT1();
        __syncthreads();
        const int kn = kt + 2;
        if (kn < KT) issue(kn, kn % 3);
        CP_COMMIT();

        const unsigned abase = sbase + (unsigned)((kt % 3) * STAGE_H) * 2;
        const unsigned bbase = abase + (unsigned)TILE_H * 2;

#pragma unroll
        for (int ks = 0; ks < 2; ks++) {
            unsigned af[4][4], bf[4][2];
#pragma unroll
            for (int mi = 0; mi < 4; mi++)
                ldmx4(af[mi], abase +
                      ((wm * 64 + mi * 16 + a_row) * PITCH + ks * 16 + a_col) * 2);
#pragma unroll
            for (int p = 0; p < 2; p++) {
                unsigned r[4];
                ldmx4(r, bbase +
                      ((wn * 32 + 16 * p + b_row) * PITCH + ks * 16 + b_col) * 2);
                bf[2 * p][0] = r[0]; bf[2 * p][1] = r[1];
                bf[2 * p + 1][0] = r[2]; bf[2 * p + 1][1] = r[3];
            }
#pragma unroll
            for (int mi = 0; mi < 4; mi++)
#pragma unroll
                for (int ni = 0; ni < 4; ni++)
                    mma_f16(c[mi][ni], af[mi], bf[ni]);
        }
    }

    // epilogue
#pragma unroll
    for (int mi = 0; mi < 4; mi++) {
        int row = by * 128 + wm * 64 + mi * 16 + g;
#pragma unroll
        for (int ni = 0; ni < 4; ni++) {
            int col = bx * 128 + wn * 32 + ni * 8 + tg * 2;
            float b0 = bias[col], b1 = bias[col + 1];
            float v00 = c[mi][ni][0] + b0, v01 = c[mi][ni][1] + b1;
            float v10 = c[mi][ni][2] + b0, v11 = c[mi][ni][3] + b1;
            if (ACT == 1) {
                v00 = gelu_exact(v00); v01 = gelu_exact(v01);
                v10 = gelu_exact(v10); v11 = gelu_exact(v11);
            }
            if (OH) {
                __half* C = (__half*)Cv;
                *(__half2*)&C[(size_t)row * N + col] = __floats2half2_rn(v00, v01);
                *(__half2*)&C[(size_t)(row + 8) * N + col] = __floats2half2_rn(v10, v11);
            } else {
                float* C = (float*)Cv;
                *(float2*)&C[(size_t)row * N + col]       = make_float2(v00, v01);
                *(float2*)&C[(size_t)(row + 8) * N + col] = make_float2(v10, v11);
            }
        }
    }
}

// ---------------------------------------------------------------------------
// Flash attention v4: q-tile 128 (8 warps / 256 threads), K/V tiles of 64
// shared by all 8 warps -> K/V gmem traffic halves vs v3.
// 3-stage cp.async, ldmatrix fragments, register softmax.
// smem (halfs): Q 128x72 + 3x K 64x72 + 3x V 64x72 = 36864 halfs = 73728 B.
// ---------------------------------------------------------------------------
#define KVH 4608                       // halfs per 64x72 K or V tile
#define AQH 9216                       // halfs for 128x72 Q tile
#define ATT_SMEM ((AQH + 6 * KVH) * 2)

__global__ __launch_bounds__(256)
void attn_h4_kernel(const __half* __restrict__ qkv, __half* __restrict__ out)
{
    extern __shared__ __half ash[];
    const unsigned sbase = smaddr(ash);

    const int qt = gridDim.x - 1 - blockIdx.x;     // heavy tiles first
    const int h = blockIdx.y, b = blockIdx.z;
    const int t = threadIdx.x, lane = t & 31, w = t >> 5;
    const int g = lane >> 2, tg = lane & 3;

    // Q tile: 128 rows x 64 halfs = 1024 16B-chunks, 4 per thread
    const __half* qbase = qkv + (size_t)(b * SEQ + qt * 128) * (3 * DMODEL) + h * DHEAD;
#pragma unroll
    for (int i = 0; i < 4; i++) {
        int f = t + 256 * i;
        int r = f >> 3, c = (f & 7) * 8;
        *(uint4*)&ash[r * 72 + c] =
            *(const uint4*)(qbase + (size_t)r * (3 * DMODEL) + c);
    }

    // K/V tile loads: 64x64 halfs = 512 chunks each, 2 per thread
    const int kr0 = t >> 3,           kc0 = (t & 7) * 8;
    const int kr1 = (t + 256) >> 3,   kc1 = ((t + 256) & 7) * 8;

    auto issue = [&](int kt, int buf) {
        const __half* kb = qkv + (size_t)(b * SEQ + kt * 64) * (3 * DMODEL)
                         + DMODEL + h * DHEAD;
        const __half* vb = kb + DMODEL;
        const unsigned kd = sbase + (unsigned)(AQH + KVH * buf) * 2;
        const unsigned vd = sbase + (unsigned)(AQH + KVH * (3 + buf)) * 2;
        cp16(kd + (kr0 * 72 + kc0) * 2, kb + (size_t)kr0 * (3 * DMODEL) + kc0);
        cp16(kd + (kr1 * 72 + kc1) * 2, kb + (size_t)kr1 * (3 * DMODEL) + kc1);
        cp16(vd + (kr0 * 72 + kc0) * 2, vb + (size_t)kr0 * (3 * DMODEL) + kc0);
        cp16(vd + (kr1 * 72 + kc1) * 2, vb + (size_t)kr1 * (3 * DMODEL) + kc1);
    };

    const int kmax = 2 * qt + 1;       // last k-tile index

    issue(0, 0); CP_COMMIT();
    if (kmax >= 1) issue(1, 1);
    CP_COMMIT();
    __syncthreads();

    // Q fragments (hoisted): warp w owns q rows [w*16, w*16+16)
    const int a_row = (lane & 15), a_col = (lane >> 4) * 8;
    unsigned qf[4][4];
#pragma unroll
    for (int ks = 0; ks < 4; ks++)
        ldmx4(qf[ks], sbase + ((w * 16 + a_row) * 72 + ks * 16 + a_col) * 2);

    const int b_row = ((lane >> 4) << 3) + (lane & 7);
    const int b_col = ((lane >> 3) & 1) * 8;
    const int v_row = ((lane >> 3) & 1) * 8 + (lane & 7);
    const int v_col = (lane >> 4) * 8;

    float m0 = -INFINITY, m1 = -INFINITY, l0 = 0.f, l1 = 0.f;
    float co[8][4];
#pragma unroll
    for (int ni = 0; ni < 8; ni++)
#pragma unroll
        for (int k = 0; k < 4; k++) co[ni][k] = 0.f;

    const int qr = qt * 128 + w * 16 + g;

    for (int kt = 0; kt <= kmax; kt++) {
        CP_WAIT1();
        __syncthreads();
        const int buf = kt % 3;
        const unsigned kb = sbase + (unsigned)(AQH + KVH * buf) * 2;
        const unsigned vb = sbase + (unsigned)(AQH + KVH * (3 + buf)) * 2;

        // ---- S = Q @ K^T ----
        float cs[8][4];
#pragma unroll
        for (int ni = 0; ni < 8; ni++)
#pragma unroll
            for (int k = 0; k < 4; k++) cs[ni][k] = 0.f;

#pragma unroll
        for (int ks = 0; ks < 4; ks++) {
            unsigned bf[8][2];
#pragma unroll
            for (int p = 0; p < 4; p++) {
                unsigned r[4];
                ldmx4(r, kb + ((16 * p + b_row) * 72 + ks * 16 + b_col) * 2);
                bf[2 * p][0] = r[0]; bf[2 * p][1] = r[1];
                bf[2 * p + 1][0] = r[2]; bf[2 * p + 1][1] = r[3];
            }
#pragma unroll
            for (int ni = 0; ni < 8; ni++)
                mma_f16(cs[ni], qf[ks], bf[ni]);
        }

        // scale + causal mask (only last two k-tiles can cross the diagonal)
        const bool diag = (kt >= 2 * qt);
#pragma unroll
        for (int ni = 0; ni < 8; ni++) {
            cs[ni][0] *= 0.125f; cs[ni][1] *= 0.125f;
            cs[ni][2] *= 0.125f; cs[ni][3] *= 0.125f;
            if (diag) {
                int kg = kt * 64 + ni * 8 + tg * 2;
                if (kg     > qr)     cs[ni][0] = -INFINITY;
                if (kg + 1 > qr)     cs[ni][1] = -INFINITY;
                if (kg     > qr + 8) cs[ni][2] = -INFINITY;
                if (kg + 1 > qr + 8) cs[ni][3] = -INFINITY;
            }
        }

        // ---- register online softmax ----
        float mx0 = -INFINITY, mx1 = -INFINITY;
#pragma unroll
        for (int ni = 0; ni < 8; ni++) {
            mx0 = fmaxf(mx0, fmaxf(cs[ni][0], cs[ni][1]));
            mx1 = fmaxf(mx1, fmaxf(cs[ni][2], cs[ni][3]));
        }
        mx0 = fmaxf(mx0, __shfl_xor_sync(0xffffffffu, mx0, 1));
        mx0 = fmaxf(mx0, __shfl_xor_sync(0xffffffffu, mx0, 2));
        mx1 = fmaxf(mx1, __shfl_xor_sync(0xffffffffu, mx1, 1));
        mx1 = fmaxf(mx1, __shfl_xor_sync(0xffffffffu, mx1, 2));

        float mt0 = fmaxf(m0, mx0), mt1 = fmaxf(m1, mx1);
        float a0 = __expf(m0 - mt0), a1 = __expf(m1 - mt1);
        m0 = mt0; m1 = mt1;

        float ps0 = 0.f, ps1 = 0.f;
#pragma unroll
        for (int ni = 0; ni < 8; ni++) {
            cs[ni][0] = __expf(cs[ni][0] - mt0);
            cs[ni][1] = __expf(cs[ni][1] - mt0);
            cs[ni][2] = __expf(cs[ni][2] - mt1);
            cs[ni][3] = __expf(cs[ni][3] - mt1);
            ps0 += cs[ni][0] + cs[ni][1];
            ps1 += cs[ni][2] + cs[ni][3];
        }
        ps0 += __shfl_xor_sync(0xffffffffu, ps0, 1);
        ps0 += __shfl_xor_sync(0xffffffffu, ps0, 2);
        ps1 += __shfl_xor_sync(0xffffffffu, ps1, 1);
        ps1 += __shfl_xor_sync(0xffffffffu, ps1, 2);
        l0 = l0 * a0 + ps0;
        l1 = l1 * a1 + ps1;

#pragma unroll
        for (int ni = 0; ni < 8; ni++) {
            co[ni][0] *= a0; co[ni][1] *= a0;
            co[ni][2] *= a1; co[ni][3] *= a1;
        }

        // ---- O += P @ V ----
#pragma unroll
        for (int ks = 0; ks < 4; ks++) {
            unsigned af[4];
            af[0] = pack2(cs[2 * ks][0],     cs[2 * ks][1]);
            af[1] = pack2(cs[2 * ks][2],     cs[2 * ks][3]);
            af[2] = pack2(cs[2 * ks + 1][0], cs[2 * ks + 1][1]);
            af[3] = pack2(cs[2 * ks + 1][2], cs[2 * ks + 1][3]);
            unsigned bf[8][2];
#pragma unroll
            for (int p = 0; p < 4; p++) {
                unsigned r[4];
                ldmx4t(r, vb + ((ks * 16 + v_row) * 72 + 16 * p + v_col) * 2);
                bf[2 * p][0] = r[0]; bf[2 * p][1] = r[1];
                bf[2 * p + 1][0] = r[2]; bf[2 * p + 1][1] = r[3];
            }
#pragma unroll
            for (int ni = 0; ni < 8; ni++)
                mma_f16(co[ni], af, bf[ni]);
        }

        if (kt + 2 <= kmax) issue(kt + 2, (kt + 2) % 3);
        CP_COMMIT();
    }

    // normalize + store fp16
    float llo = 1.f / l0, lhi = 1.f / l1;
    int row0 = b * SEQ + qt * 128 + w * 16 + g;
    __half* ob = out + (size_t)row0 * DMODEL + h * DHEAD;
#pragma unroll
    for (int ni = 0; ni < 8; ni++) {
        int col = ni * 8 + tg * 2;
        *(__half2*)&ob[col] =
            __floats2half2_rn(co[ni][0] * llo, co[ni][1] * llo);
        *(__half2*)&ob[(size_t)8 * DMODEL + col] =
            __floats2half2_rn(co[ni][2] * lhi, co[ni][3] * lhi);
    }
}

// ---------------------------------------------------------------------------
// Fused residual add + LayerNorm (+ optional fp16 copy)
// ---------------------------------------------------------------------------
template<bool H16>
__global__ __launch_bounds__(256)
void ln_kernel(const float* __restrict__ A, const float* __restrict__ B,
               const float* __restrict__ g, const float* __restrict__ be,
               float* __restrict__ out, __half* __restrict__ out16)
{
    const int row = blockIdx.x;
    const size_t off = (size_t)row * DMODEL;
    const int t = threadIdx.x;

    float4 a = ((const float4*)(A + off))[t];
    float4 b = ((const float4*)(B + off))[t];
    float x0 = a.x + b.x, x1 = a.y + b.y, x2 = a.z + b.z, x3 = a.w + b.w;

    float s  = x0 + x1 + x2 + x3;
    float s2 = x0 * x0 + x1 * x1 + x2 * x2 + x3 * x3;
#pragma unroll
    for (int o = 16; o; o >>= 1) {
        s  += __shfl_xor_sync(0xffffffffu, s, o);
        s2 += __shfl_xor_sync(0xffffffffu, s2, o);
    }
    __shared__ float ws[8], ws2[8];
    if ((t & 31) == 0) { ws[t >> 5] = s; ws2[t >> 5] = s2; }
    __syncthreads();
    s = 0.f; s2 = 0.f;
#pragma unroll
    for (int i = 0; i < 8; i++) { s += ws[i]; s2 += ws2[i]; }

    const float mean = s * (1.f / DMODEL);
    const float var  = s2 * (1.f / DMODEL) - mean * mean;
    const float rstd = rsqrtf(var + LN_EPS);

    float4 gg = ((const float4*)g)[t];
    float4 bb = ((const float4*)be)[t];
    float4 y;
    y.x = (x0 - mean) * rstd * gg.x + bb.x;
    y.y = (x1 - mean) * rstd * gg.y + bb.y;
    y.z = (x2 - mean) * rstd * gg.z + bb.z;
    y.w = (x3 - mean) * rstd * gg.w + bb.w;
    ((float4*)(out + off))[t] = y;
    if (H16) {
        uint2 u;
        u.x = pack2(y.x, y.y);
        u.y = pack2(y.z, y.w);
        ((uint2*)(out16 + off))[t] = u;
    }
}

// ---------------------------------------------------------------------------
// Launcher
// ---------------------------------------------------------------------------
extern "C" void kernel_launch(void* const* d_in, const int* in_sizes, int n_in,
                              void* d_out, int out_size)
{
    const float* X     = (const float*)d_in[0];
    const float* W_qkv = (const float*)d_in[1];
    const float* b_qkv = (const float*)d_in[2];
    const float* W_o   = (const float*)d_in[3];
    const float* b_o   = (const float*)d_in[4];
    const float* W_1   = (const float*)d_in[5];
    const float* b_1   = (const float*)d_in[6];
    const float* W_2   = (const float*)d_in[7];
    const float* b_2   = (const float*)d_in[8];
    const float* ln1g  = (const float*)d_in[9];
    const float* ln1b  = (const float*)d_in[10];
    const float* ln2g  = (const float*)d_in[11];
    const float* ln2b  = (const float*)d_in[12];
    float* out = (float*)d_out;

    __half *xh, *qkv, *attn, *ffn, *h1h, *wt;
    float *h1, *tmp;
    cudaGetSymbolAddress((void**)&xh,   g_xh);
    cudaGetSymbolAddress((void**)&qkv,  g_qkv);
    cudaGetSymbolAddress((void**)&attn, g_attn);
    cudaGetSymbolAddress((void**)&ffn,  g_ffn);
    cudaGetSymbolAddress((void**)&h1,   g_h1);
    cudaGetSymbolAddress((void**)&h1h,  g_h1h);
    cudaGetSymbolAddress((void**)&tmp,  g_tmp);
    cudaGetSymbolAddress((void**)&wt,   g_wt);

    cudaFuncSetAttribute(hgemm2<true, 0>,
                         cudaFuncAttributeMaxDynamicSharedMemorySize, GT_SMEM);
    cudaFuncSetAttribute(hgemm2<false, 0>,
                         cudaFuncAttributeMaxDynamicSharedMemorySize, GT_SMEM);
    cudaFuncSetAttribute(hgemm2<true, 1>,
                         cudaFuncAttributeMaxDynamicSharedMemorySize, GT_SMEM);
    cudaFuncSetAttribute(attn_h4_kernel,
                         cudaFuncAttributeMaxDynamicSharedMemorySize, ATT_SMEM);

    // 0) conversions
    f2h_kernel<<<ROWS * DMODEL / 1024, 256>>>(X, xh);
    transpose_h<<<dim3(3 * DMODEL / 32, DMODEL / 32), 256>>>(W_qkv, wt + WT_QKV, DMODEL, 3 * DMODEL);
    transpose_h<<<dim3(DMODEL / 32, DMODEL / 32), 256>>>(W_o, wt + WT_O, DMODEL, DMODEL);
    transpose_h<<<dim3(DFF / 32, DMODEL / 32), 256>>>(W_1, wt + WT_1, DMODEL, DFF);
    transpose_h<<<dim3(DMODEL / 32, DFF / 32), 256>>>(W_2, wt + WT_2, DFF, DMODEL);

    // 1) QKV projection
    hgemm2<true, 0><<<dim3(3 * DMODEL / 128, ROWS / 128), 256, GT_SMEM>>>(
        xh, wt + WT_QKV, b_qkv, qkv, ROWS, 3 * DMODEL, DMODEL);

    // 2) causal flash attention (q-tile 128)
    attn_h4_kernel<<<dim3(SEQ / 128, NHEADS, BATCH), 256, ATT_SMEM>>>(qkv, attn);

    // 3) output projection -> tmp (fp32)
    hgemm2<false, 0><<<dim3(DMODEL / 128, ROWS / 128), 256, GT_SMEM>>>(
        attn, wt + WT_O, b_o, tmp, ROWS, DMODEL, DMODEL);

    // 4) H1 = LN(X + O), fp32 + fp16
    ln_kernel<true><<<ROWS, 256>>>(X, tmp, ln1g, ln1b, h1, h1h);

    // 5) FF1 + GELU
    hgemm2<true, 1><<<dim3(DFF / 128, ROWS / 128), 256, GT_SMEM>>>(
        h1h, wt + WT_1, b_1, ffn, ROWS, DFF, DMODEL);

    // 6) FF2 -> tmp (fp32)
    hgemm2<false, 0><<<dim3(DMODEL / 128, ROWS / 128), 256, GT_SMEM>>>(
        ffn, wt + WT_2, b_2, tmp, ROWS, DMODEL, DFF);

    // 7) out = LN(H1 + H2)
    ln_kernel<false><<<ROWS, 256>>>(h1, tmp, ln2g, ln2b, out, nullptr);
}

// round 9
// speedup vs baseline: 1.1670x; 1.0964x over previous
#include <cuda_runtime.h>
#include <cuda_fp16.h>
#include <math.h>
#include <stdint.h>

// ---------------------------------------------------------------------------
// Problem constants
// ---------------------------------------------------------------------------
#define BATCH   2
#define SEQ     2048
#define DMODEL  1024
#define DFF     4096
#define NHEADS  16
#define DHEAD   64
#define ROWS    (BATCH * SEQ)
#define LN_EPS  1e-5f

// ---------------------------------------------------------------------------
// Scratch — __device__ globals
// ---------------------------------------------------------------------------
__device__ __half g_xh  [(size_t)ROWS * DMODEL];
__device__ __half g_qkv [(size_t)ROWS * 3 * DMODEL];
__device__ __half g_attn[(size_t)ROWS * DMODEL];
__device__ __half g_ffn [(size_t)ROWS * DFF];
__device__ float  g_h1  [(size_t)ROWS * DMODEL];
__device__ __half g_h1h [(size_t)ROWS * DMODEL];
__device__ float  g_tmp [(size_t)ROWS * DMODEL];
__device__ __half g_wt  [(size_t)12288 * 1024];

#define WT_QKV 0
#define WT_O   (3072 * 1024)
#define WT_1   (WT_O + 1024 * 1024)
#define WT_2   (WT_1 + 4096 * 1024)

// ---------------------------------------------------------------------------
// helpers
// ---------------------------------------------------------------------------
__device__ __forceinline__ unsigned pack2(float x, float y) {
    __half2 h = __floats2half2_rn(x, y);
    return *reinterpret_cast<unsigned*>(&h);
}

__device__ __forceinline__ void mma_f16(float c[4], const unsigned a[4],
                                        const unsigned b[2]) {
    asm volatile(
        "mma.sync.aligned.m16n8k16.row.col.f32.f16.f16.f32 "
        "{%0,%1,%2,%3},{%4,%5,%6,%7},{%8,%9},{%0,%1,%2,%3};"
        : "+f"(c[0]), "+f"(c[1]), "+f"(c[2]), "+f"(c[3])
        : "r"(a[0]), "r"(a[1]), "r"(a[2]), "r"(a[3]), "r"(b[0]), "r"(b[1]));
}

__device__ __forceinline__ unsigned smaddr(const void* p) {
    unsigned a;
    asm("{\n\t.reg .u64 t;\n\tcvta.to.shared.u64 t, %1;\n\tcvt.u32.u64 %0, t;\n\t}"
        : "=r"(a) : "l"(p));
    return a;
}

__device__ __forceinline__ void ldmx4(unsigned r[4], unsigned a) {
    asm volatile("ldmatrix.sync.aligned.m8n8.x4.shared.b16 {%0,%1,%2,%3}, [%4];"
        : "=r"(r[0]), "=r"(r[1]), "=r"(r[2]), "=r"(r[3]) : "r"(a));
}
__device__ __forceinline__ void ldmx4t(unsigned r[4], unsigned a) {
    asm volatile("ldmatrix.sync.aligned.m8n8.x4.trans.shared.b16 {%0,%1,%2,%3}, [%4];"
        : "=r"(r[0]), "=r"(r[1]), "=r"(r[2]), "=r"(r[3]) : "r"(a));
}

__device__ __forceinline__ void cp16(unsigned dst, const void* src) {
    asm volatile("cp.async.cg.shared.global [%0], [%1], 16;"
                 :: "r"(dst), "l"(src));
}
#define CP_COMMIT() asm volatile("cp.async.commit_group;" ::: "memory")
#define CP_WAIT1()  asm volatile("cp.async.wait_group 1;"  ::: "memory")

__device__ __forceinline__ float gelu_exact(float x) {
    return 0.5f * x * (1.f + erff(x * 0.70710678118654752f));
}

// ---------------------------------------------------------------------------
// X -> fp16
// ---------------------------------------------------------------------------
__global__ __launch_bounds__(256)
void f2h_kernel(const float* __restrict__ in, __half* __restrict__ out)
{
    int i = blockIdx.x * 256 + threadIdx.x;
    float4 v = ((const float4*)in)[i];
    uint2 u;
    u.x = pack2(v.x, v.y);
    u.y = pack2(v.z, v.w);
    ((uint2*)out)[i] = u;
}

// ---------------------------------------------------------------------------
// Weight transpose + fp16 convert
// ---------------------------------------------------------------------------
__global__ __launch_bounds__(256)
void transpose_h(const float* __restrict__ in, __half* __restrict__ out,
                 int R, int C)
{
    __shared__ float tile[32][33];
    const int c0 = blockIdx.x * 32, r0 = blockIdx.y * 32;
    const int tx = threadIdx.x & 31, ty = threadIdx.x >> 5;
#pragma unroll
    for (int i = ty; i < 32; i += 8)
        tile[i][tx] = in[(size_t)(r0 + i) * C + c0 + tx];
    __syncthreads();
#pragma unroll
    for (int i = ty; i < 32; i += 8)
        out[(size_t)(c0 + i) * R + r0 + tx] = __float2half(tile[tx][i]);
}

// ---------------------------------------------------------------------------
// fp16 GEMM v4: BM=BN=128, BK=64, 3-stage cp.async, ldmatrix fragments.
// 256 threads (8 warps 2x4), warp tile 64x32. Half the barriers of BK=32.
// smem: 3 stages x 2 tiles x (128x72 halfs) = 110592 B.
// ---------------------------------------------------------------------------
#define PITCH 72
#define TILE_H (128 * PITCH)
#define STAGE_H (2 * TILE_H)
#define GT_SMEM (3 * STAGE_H * 2)

template<bool OH, int ACT>
__global__ __launch_bounds__(256)
void hgemm4(const __half* __restrict__ A, const __half* __restrict__ Bt,
            const float* __restrict__ bias, void* __restrict__ Cv,
            int M, int N, int K)
{
    extern __shared__ __half sm2[];
    const unsigned sbase = smaddr(sm2);

    const int tid = threadIdx.x, lane = tid & 31, warp = tid >> 5;
    const int wm = warp >> 2, wn = warp & 3;
    const int g = lane >> 2, tg = lane & 3;
    const int bx = blockIdx.x, by = blockIdx.y;

    const __half* Abase = A  + (size_t)(by * 128) * K;
    const __half* Bbase = Bt + (size_t)(bx * 128) * K;
    const int KT = K / 64;

    // per-tile: 128 rows x 8 chunks(16B) = 1024 chunks; 4 per thread per operand
    auto issue = [&](int kt, int slot) {
        const unsigned sa = sbase + (unsigned)(slot * STAGE_H) * 2;
        const unsigned sb = sa + (unsigned)TILE_H * 2;
        const int ko = kt * 64;
#pragma unroll
        for (int i = 0; i < 4; i++) {
            int f = tid + 256 * i;
            int r = f >> 3, kc = (f & 7) * 8;
            cp16(sa + (r * PITCH + kc) * 2, Abase + (size_t)r * K + ko + kc);
            cp16(sb + (r * PITCH + kc) * 2, Bbase + (size_t)r * K + ko + kc);
        }
    };

    float c[4][4][4];
#pragma unroll
    for (int mi = 0; mi < 4; mi++)
#pragma unroll
        for (int ni = 0; ni < 4; ni++)
#pragma unroll
            for (int k = 0; k < 4; k++) c[mi][ni][k] = 0.f;

    issue(0, 0); CP_COMMIT();
    if (KT > 1) issue(1, 1);
    CP_COMMIT();

    const int a_row = (lane & 15);
    const int a_col = (lane >> 4) * 8;
    const int b_row = ((lane >> 4) << 3) + (lane & 7);
    const int b_col = ((lane >> 3) & 1) * 8;

    for (int kt = 0; kt < KT; kt++) {
        CP_WAIT1();
        __syncthreads();
        const int kn = kt + 2;
        if (kn < KT) issue(kn, kn % 3);
        CP_COMMIT();

        const unsigned abase = sbase + (unsigned)((kt % 3) * STAGE_H) * 2;
        const unsigned bbase = abase + (unsigned)TILE_H * 2;

#pragma unroll
        for (int ks = 0; ks < 4; ks++) {
            unsigned af[4][4], bf[4][2];
#pragma unroll
            for (int mi = 0; mi < 4; mi++)
                ldmx4(af[mi], abase +
                      ((wm * 64 + mi * 16 + a_row) * PITCH + ks * 16 + a_col) * 2);
#pragma unroll
            for (int p = 0; p < 2; p++) {
                unsigned r[4];
                ldmx4(r, bbase +
                      ((wn * 32 + 16 * p + b_row) * PITCH + ks * 16 + b_col) * 2);
                bf[2 * p][0] = r[0]; bf[2 * p][1] = r[1];
                bf[2 * p + 1][0] = r[2]; bf[2 * p + 1][1] = r[3];
            }
#pragma unroll
            for (int mi = 0; mi < 4; mi++)
#pragma unroll
                for (int ni = 0; ni < 4; ni++)
                    mma_f16(c[mi][ni], af[mi], bf[ni]);
        }
    }

    // epilogue
#pragma unroll
    for (int mi = 0; mi < 4; mi++) {
        int row = by * 128 + wm * 64 + mi * 16 + g;
#pragma unroll
        for (int ni = 0; ni < 4; ni++) {
            int col = bx * 128 + wn * 32 + ni * 8 + tg * 2;
            float b0 = bias[col], b1 = bias[col + 1];
            float v00 = c[mi][ni][0] + b0, v01 = c[mi][ni][1] + b1;
            float v10 = c[mi][ni][2] + b0, v11 = c[mi][ni][3] + b1;
            if (ACT == 1) {
                v00 = gelu_exact(v00); v01 = gelu_exact(v01);
                v10 = gelu_exact(v10); v11 = gelu_exact(v11);
            }
            if (OH) {
                __half* C = (__half*)Cv;
                *(__half2*)&C[(size_t)row * N + col] = __floats2half2_rn(v00, v01);
                *(__half2*)&C[(size_t)(row + 8) * N + col] = __floats2half2_rn(v10, v11);
            } else {
                float* C = (float*)Cv;
                *(float2*)&C[(size_t)row * N + col]       = make_float2(v00, v01);
                *(float2*)&C[(size_t)(row + 8) * N + col] = make_float2(v10, v11);
            }
        }
    }
}

// ---------------------------------------------------------------------------
// Flash attention v3 (exact R6 winner): q-tile 64, 4 warps,
// 3-stage cp.async K/V, ldmatrix fragments, register softmax.
// ---------------------------------------------------------------------------
#define QH 4608
#define ATT_SMEM (7 * QH * 2)

__global__ __launch_bounds__(128)
void attn_h3_kernel(const __half* __restrict__ qkv, __half* __restrict__ out)
{
    extern __shared__ __half ash[];
    const unsigned sbase = smaddr(ash);

    const int qt = gridDim.x - 1 - blockIdx.x;
    const int h = blockIdx.y, b = blockIdx.z;
    const int t = threadIdx.x, lane = t & 31, w = t >> 5;
    const int g = lane >> 2, tg = lane & 3;

    const int lr[4] = { t >> 3, (t + 128) >> 3, (t + 256) >> 3, (t + 384) >> 3 };
    const int lc    = (t & 7) * 8;

    const __half* qbase = qkv + (size_t)(b * SEQ + qt * 64) * (3 * DMODEL) + h * DHEAD;
#pragma unroll
    for (int i = 0; i < 4; i++)
        *(uint4*)&ash[lr[i] * 72 + lc] =
            *(const uint4*)(qbase + (size_t)lr[i] * (3 * DMODEL) + lc);

    auto issue = [&](int kt, int buf) {
        const __half* kb = qkv + (size_t)(b * SEQ + kt * 64) * (3 * DMODEL)
                         + DMODEL + h * DHEAD;
        const __half* vb = kb + DMODEL;
        const unsigned kd = sbase + (unsigned)(QH * (1 + buf)) * 2;
        const unsigned vd = sbase + (unsigned)(QH * (4 + buf)) * 2;
#pragma unroll
        for (int i = 0; i < 4; i++) {
            cp16(kd + (lr[i] * 72 + lc) * 2, kb + (size_t)lr[i] * (3 * DMODEL) + lc);
            cp16(vd + (lr[i] * 72 + lc) * 2, vb + (size_t)lr[i] * (3 * DMODEL) + lc);
        }
    };

    issue(0, 0); CP_COMMIT();
    if (qt >= 1) issue(1, 1);
    CP_COMMIT();
    __syncthreads();

    const int a_row = (lane & 15), a_col = (lane >> 4) * 8;
    unsigned qf[4][4];
#pragma unroll
    for (int ks = 0; ks < 4; ks++)
        ldmx4(qf[ks], sbase + ((w * 16 + a_row) * 72 + ks * 16 + a_col) * 2);

    const int b_row = ((lane >> 4) << 3) + (lane & 7);
    const int b_col = ((lane >> 3) & 1) * 8;
    const int v_row = ((lane >> 3) & 1) * 8 + (lane & 7);
    const int v_col = (lane >> 4) * 8;

    float m0 = -INFINITY, m1 = -INFINITY, l0 = 0.f, l1 = 0.f;
    float co[8][4];
#pragma unroll
    for (int ni = 0; ni < 8; ni++)
#pragma unroll
        for (int k = 0; k < 4; k++) co[ni][k] = 0.f;

    const int qr = qt * 64 + w * 16 + g;

    for (int kt = 0; kt <= qt; kt++) {
        CP_WAIT1();
        __syncthreads();
        const int buf = kt % 3;
        const unsigned kb = sbase + (unsigned)(QH * (1 + buf)) * 2;
        const unsigned vb = sbase + (unsigned)(QH * (4 + buf)) * 2;

        float cs[8][4];
#pragma unroll
        for (int ni = 0; ni < 8; ni++)
#pragma unroll
            for (int k = 0; k < 4; k++) cs[ni][k] = 0.f;

#pragma unroll
        for (int ks = 0; ks < 4; ks++) {
            unsigned bf[8][2];
#pragma unroll
            for (int p = 0; p < 4; p++) {
                unsigned r[4];
                ldmx4(r, kb + ((16 * p + b_row) * 72 + ks * 16 + b_col) * 2);
                bf[2 * p][0] = r[0]; bf[2 * p][1] = r[1];
                bf[2 * p + 1][0] = r[2]; bf[2 * p + 1][1] = r[3];
            }
#pragma unroll
            for (int ni = 0; ni < 8; ni++)
                mma_f16(cs[ni], qf[ks], bf[ni]);
        }

        const bool diag = (kt == qt);
#pragma unroll
        for (int ni = 0; ni < 8; ni++) {
            cs[ni][0] *= 0.125f; cs[ni][1] *= 0.125f;
            cs[ni][2] *= 0.125f; cs[ni][3] *= 0.125f;
            if (diag) {
                int kg = kt * 64 + ni * 8 + tg * 2;
                if (kg     > qr)     cs[ni][0] = -INFINITY;
                if (kg + 1 > qr)     cs[ni][1] = -INFINITY;
                if (kg     > qr + 8) cs[ni][2] = -INFINITY;
                if (kg + 1 > qr + 8) cs[ni][3] = -INFINITY;
            }
        }

        float mx0 = -INFINITY, mx1 = -INFINITY;
#pragma unroll
        for (int ni = 0; ni < 8; ni++) {
            mx0 = fmaxf(mx0, fmaxf(cs[ni][0], cs[ni][1]));
            mx1 = fmaxf(mx1, fmaxf(cs[ni][2], cs[ni][3]));
        }
        mx0 = fmaxf(mx0, __shfl_xor_sync(0xffffffffu, mx0, 1));
        mx0 = fmaxf(mx0, __shfl_xor_sync(0xffffffffu, mx0, 2));
        mx1 = fmaxf(mx1, __shfl_xor_sync(0xffffffffu, mx1, 1));
        mx1 = fmaxf(mx1, __shfl_xor_sync(0xffffffffu, mx1, 2));

        float mt0 = fmaxf(m0, mx0), mt1 = fmaxf(m1, mx1);
        float a0 = __expf(m0 - mt0), a1 = __expf(m1 - mt1);
        m0 = mt0; m1 = mt1;

        float ps0 = 0.f, ps1 = 0.f;
#pragma unroll
        for (int ni = 0; ni < 8; ni++) {
            cs[ni][0] = __expf(cs[ni][0] - mt0);
            cs[ni][1] = __expf(cs[ni][1] - mt0);
            cs[ni][2] = __expf(cs[ni][2] - mt1);
            cs[ni][3] = __expf(cs[ni][3] - mt1);
            ps0 += cs[ni][0] + cs[ni][1];
            ps1 += cs[ni][2] + cs[ni][3];
        }
        ps0 += __shfl_xor_sync(0xffffffffu, ps0, 1);
        ps0 += __shfl_xor_sync(0xffffffffu, ps0, 2);
        ps1 += __shfl_xor_sync(0xffffffffu, ps1, 1);
        ps1 += __shfl_xor_sync(0xffffffffu, ps1, 2);
        l0 = l0 * a0 + ps0;
        l1 = l1 * a1 + ps1;

#pragma unroll
        for (int ni = 0; ni < 8; ni++) {
            co[ni][0] *= a0; co[ni][1] *= a0;
            co[ni][2] *= a1; co[ni][3] *= a1;
        }

#pragma unroll
        for (int ks = 0; ks < 4; ks++) {
            unsigned af[4];
            af[0] = pack2(cs[2 * ks][0],     cs[2 * ks][1]);
            af[1] = pack2(cs[2 * ks][2],     cs[2 * ks][3]);
            af[2] = pack2(cs[2 * ks + 1][0], cs[2 * ks + 1][1]);
            af[3] = pack2(cs[2 * ks + 1][2], cs[2 * ks + 1][3]);
            unsigned bf[8][2];
#pragma unroll
            for (int p = 0; p < 4; p++) {
                unsigned r[4];
                ldmx4t(r, vb + ((ks * 16 + v_row) * 72 + 16 * p + v_col) * 2);
                bf[2 * p][0] = r[0]; bf[2 * p][1] = r[1];
                bf[2 * p + 1][0] = r[2]; bf[2 * p + 1][1] = r[3];
            }
#pragma unroll
            for (int ni = 0; ni < 8; ni++)
                mma_f16(co[ni], af, bf[ni]);
        }

        if (kt + 2 <= qt) issue(kt + 2, (kt + 2) % 3);
        CP_COMMIT();
    }

    float llo = 1.f / l0, lhi = 1.f / l1;
    int row0 = b * SEQ + qt * 64 + w * 16 + g;
    __half* ob = out + (size_t)row0 * DMODEL + h * DHEAD;
#pragma unroll
    for (int ni = 0; ni < 8; ni++) {
        int col = ni * 8 + tg * 2;
        *(__half2*)&ob[col] =
            __floats2half2_rn(co[ni][0] * llo, co[ni][1] * llo);
        *(__half2*)&ob[(size_t)8 * DMODEL + col] =
            __floats2half2_rn(co[ni][2] * lhi, co[ni][3] * lhi);
    }
}

// ---------------------------------------------------------------------------
// Fused residual add + LayerNorm (+ optional fp16 copy)
// ---------------------------------------------------------------------------
template<bool H16>
__global__ __launch_bounds__(256)
void ln_kernel(const float* __restrict__ A, const float* __restrict__ B,
               const float* __restrict__ g, const float* __restrict__ be,
               float* __restrict__ out, __half* __restrict__ out16)
{
    const int row = blockIdx.x;
    const size_t off = (size_t)row * DMODEL;
    const int t = threadIdx.x;

    float4 a = ((const float4*)(A + off))[t];
    float4 b = ((const float4*)(B + off))[t];
    float x0 = a.x + b.x, x1 = a.y + b.y, x2 = a.z + b.z, x3 = a.w + b.w;

    float s  = x0 + x1 + x2 + x3;
    float s2 = x0 * x0 + x1 * x1 + x2 * x2 + x3 * x3;
#pragma unroll
    for (int o = 16; o; o >>= 1) {
        s  += __shfl_xor_sync(0xffffffffu, s, o);
        s2 += __shfl_xor_sync(0xffffffffu, s2, o);
    }
    __shared__ float ws[8], ws2[8];
    if ((t & 31) == 0) { ws[t >> 5] = s; ws2[t >> 5] = s2; }
    __syncthreads();
    s = 0.f; s2 = 0.f;
#pragma unroll
    for (int i = 0; i < 8; i++) { s += ws[i]; s2 += ws2[i]; }

    const float mean = s * (1.f / DMODEL);
    const float var  = s2 * (1.f / DMODEL) - mean * mean;
    const float rstd = rsqrtf(var + LN_EPS);

    float4 gg = ((const float4*)g)[t];
    float4 bb = ((const float4*)be)[t];
    float4 y;
    y.x = (x0 - mean) * rstd * gg.x + bb.x;
    y.y = (x1 - mean) * rstd * gg.y + bb.y;
    y.z = (x2 - mean) * rstd * gg.z + bb.z;
    y.w = (x3 - mean) * rstd * gg.w + bb.w;
    ((float4*)(out + off))[t] = y;
    if (H16) {
        uint2 u;
        u.x = pack2(y.x, y.y);
        u.y = pack2(y.z, y.w);
        ((uint2*)(out16 + off))[t] = u;
    }
}

// ---------------------------------------------------------------------------
// Launcher
// ---------------------------------------------------------------------------
extern "C" void kernel_launch(void* const* d_in, const int* in_sizes, int n_in,
                              void* d_out, int out_size)
{
    const float* X     = (const float*)d_in[0];
    const float* W_qkv = (const float*)d_in[1];
    const float* b_qkv = (const float*)d_in[2];
    const float* W_o   = (const float*)d_in[3];
    const float* b_o   = (const float*)d_in[4];
    const float* W_1   = (const float*)d_in[5];
    const float* b_1   = (const float*)d_in[6];
    const float* W_2   = (const float*)d_in[7];
    const float* b_2   = (const float*)d_in[8];
    const float* ln1g  = (const float*)d_in[9];
    const float* ln1b  = (const float*)d_in[10];
    const float* ln2g  = (const float*)d_in[11];
    const float* ln2b  = (const float*)d_in[12];
    float* out = (float*)d_out;

    __half *xh, *qkv, *attn, *ffn, *h1h, *wt;
    float *h1, *tmp;
    cudaGetSymbolAddress((void**)&xh,   g_xh);
    cudaGetSymbolAddress((void**)&qkv,  g_qkv);
    cudaGetSymbolAddress((void**)&attn, g_attn);
    cudaGetSymbolAddress((void**)&ffn,  g_ffn);
    cudaGetSymbolAddress((void**)&h1,   g_h1);
    cudaGetSymbolAddress((void**)&h1h,  g_h1h);
    cudaGetSymbolAddress((void**)&tmp,  g_tmp);
    cudaGetSymbolAddress((void**)&wt,   g_wt);

    cudaFuncSetAttribute(hgemm4<true, 0>,
                         cudaFuncAttributeMaxDynamicSharedMemorySize, GT_SMEM);
    cudaFuncSetAttribute(hgemm4<false, 0>,
                         cudaFuncAttributeMaxDynamicSharedMemorySize, GT_SMEM);
    cudaFuncSetAttribute(hgemm4<true, 1>,
                         cudaFuncAttributeMaxDynamicSharedMemorySize, GT_SMEM);
    cudaFuncSetAttribute(attn_h3_kernel,
                         cudaFuncAttributeMaxDynamicSharedMemorySize, ATT_SMEM);

    // 0) conversions
    f2h_kernel<<<ROWS * DMODEL / 1024, 256>>>(X, xh);
    transpose_h<<<dim3(3 * DMODEL / 32, DMODEL / 32), 256>>>(W_qkv, wt + WT_QKV, DMODEL, 3 * DMODEL);
    transpose_h<<<dim3(DMODEL / 32, DMODEL / 32), 256>>>(W_o, wt + WT_O, DMODEL, DMODEL);
    transpose_h<<<dim3(DFF / 32, DMODEL / 32), 256>>>(W_1, wt + WT_1, DMODEL, DFF);
    transpose_h<<<dim3(DMODEL / 32, DFF / 32), 256>>>(W_2, wt + WT_2, DFF, DMODEL);

    // 1) QKV projection
    hgemm4<true, 0><<<dim3(3 * DMODEL / 128, ROWS / 128), 256, GT_SMEM>>>(
        xh, wt + WT_QKV, b_qkv, qkv, ROWS, 3 * DMODEL, DMODEL);

    // 2) causal flash attention (R6 shape)
    attn_h3_kernel<<<dim3(SEQ / 64, NHEADS, BATCH), 128, ATT_SMEM>>>(qkv, attn);

    // 3) output projection -> tmp (fp32)
    hgemm4<false, 0><<<dim3(DMODEL / 128, ROWS / 128), 256, GT_SMEM>>>(
        attn, wt + WT_O, b_o, tmp, ROWS, DMODEL, DMODEL);

    // 4) H1 = LN(X + O), fp32 + fp16
    ln_kernel<true><<<ROWS, 256>>>(X, tmp, ln1g, ln1b, h1, h1h);

    // 5) FF1 + GELU
    hgemm4<true, 1><<<dim3(DFF / 128, ROWS / 128), 256, GT_SMEM>>>(
        h1h, wt + WT_1, b_1, ffn, ROWS, DFF, DMODEL);

    // 6) FF2 -> tmp (fp32)
    hgemm4<false, 0><<<dim3(DMODEL / 128, ROWS / 128), 256, GT_SMEM>>>(
        ffn, wt + WT_2, b_2, tmp, ROWS, DMODEL, DFF);

    // 7) out = LN(H1 + H2)
    ln_kernel<false><<<ROWS, 256>>>(h1, tmp, ln2g, ln2b, out, nullptr);
}